// round 14
// baseline (speedup 1.0000x reference)
#include <cuda_runtime.h>
#include <stdint.h>

#define DIM   2048
#define NE    64
#define TOPK  8
#define BT    128            // tokens per CTA
#define NTHR  128
#define KC    4              // k per register chunk
#define NCHK  (DIM / KC)     // 512
#define SSTR  66
#define LOG2E 1.4426950408889634f

// Transposed weights [k][expert], natural order (adjacent experts pair
// into f32x2). 512 KB, stays hot in L1/L2.
__device__ float g_wt[DIM * NE];
__device__ int   g_hist[NE];
__device__ int   g_cnt;

// ---------------- helpers ----------------
__device__ __forceinline__ void ffma2(unsigned long long &d,
                                      unsigned long long a,
                                      unsigned long long b) {
    asm("fma.rn.f32x2 %0, %1, %2, %0;" : "+l"(d) : "l"(a), "l"(b));
}
__device__ __forceinline__ unsigned long long dup2(float w) {
    unsigned long long r;
    asm("mov.b64 %0, {%1, %1};" : "=l"(r) : "f"(w));
    return r;
}
__device__ __forceinline__ float2 ull_as_f2(unsigned long long v) {
    float2 r;
    asm("mov.b64 {%0, %1}, %2;" : "=f"(r.x), "=f"(r.y) : "l"(v));
    return r;
}

// ============================================================
// Prep: transpose gate_weight [64][2048] -> g_wt [2048][64].
// ============================================================
__global__ void prep_kernel(const float* __restrict__ gw) {
    __shared__ float ts[64][68];
    const int t = threadIdx.x, blk = blockIdx.x;
    #pragma unroll
    for (int i = 0; i < 4; i++) {
        int idx = t + i * 256;
        int e = idx >> 4, q = idx & 15;
        float4 f = ((const float4*)gw)[e * 512 + blk * 16 + q];
        ts[e][q * 4 + 0] = f.x; ts[e][q * 4 + 1] = f.y;
        ts[e][q * 4 + 2] = f.z; ts[e][q * 4 + 3] = f.w;
    }
    __syncthreads();
    #pragma unroll
    for (int i = 0; i < 4; i++) {
        int idx = t + i * 256;
        int k = idx >> 4, p = idx & 15;    // slot p = experts 4p..4p+3
        ((float4*)g_wt)[(blk * 64 + k) * 16 + p] =
            make_float4(ts[p * 4 + 0][k], ts[p * 4 + 1][k],
                        ts[p * 4 + 2][k], ts[p * 4 + 3][k]);
    }
    if (blk == 0 && t < NE) g_hist[t] = 0;
    if (blk == 0 && t == 0) g_cnt = 0;
}

// one k-step: 8 x-dups (alu) + 32 FFMA2 (fma); w pairs direct from LDG.
#define COMPUTE_K(XS, WA, WB)                                        \
    do {                                                             \
        unsigned long long xd0 = dup2((XS)[0]), xd1 = dup2((XS)[1]); \
        unsigned long long xd2 = dup2((XS)[2]), xd3 = dup2((XS)[3]); \
        unsigned long long xd4 = dup2((XS)[4]), xd5 = dup2((XS)[5]); \
        unsigned long long xd6 = dup2((XS)[6]), xd7 = dup2((XS)[7]); \
        ffma2(acc[0][0], xd0, (WA).x); ffma2(acc[0][1], xd0, (WA).y); \
        ffma2(acc[0][2], xd0, (WB).x); ffma2(acc[0][3], xd0, (WB).y); \
        ffma2(acc[1][0], xd1, (WA).x); ffma2(acc[1][1], xd1, (WA).y); \
        ffma2(acc[1][2], xd1, (WB).x); ffma2(acc[1][3], xd1, (WB).y); \
        ffma2(acc[2][0], xd2, (WA).x); ffma2(acc[2][1], xd2, (WA).y); \
        ffma2(acc[2][2], xd2, (WB).x); ffma2(acc[2][3], xd2, (WB).y); \
        ffma2(acc[3][0], xd3, (WA).x); ffma2(acc[3][1], xd3, (WA).y); \
        ffma2(acc[3][2], xd3, (WB).x); ffma2(acc[3][3], xd3, (WB).y); \
        ffma2(acc[4][0], xd4, (WA).x); ffma2(acc[4][1], xd4, (WA).y); \
        ffma2(acc[4][2], xd4, (WB).x); ffma2(acc[4][3], xd4, (WB).y); \
        ffma2(acc[5][0], xd5, (WA).x); ffma2(acc[5][1], xd5, (WA).y); \
        ffma2(acc[5][2], xd5, (WB).x); ffma2(acc[5][3], xd5, (WB).y); \
        ffma2(acc[6][0], xd6, (WA).x); ffma2(acc[6][1], xd6, (WA).y); \
        ffma2(acc[6][2], xd6, (WB).x); ffma2(acc[6][3], xd6, (WB).y); \
        ffma2(acc[7][0], xd7, (WA).x); ffma2(acc[7][1], xd7, (WA).y); \
        ffma2(acc[7][2], xd7, (WB).x); ffma2(acc[7][3], xd7, (WB).y); \
    } while (0)

// ============================================================
// Fused gate kernel. CTA: 128 tok x 64 exp, 128 threads; grid 256.
// NO shared memory and NO syncs in the mainloop: x lives in a
// register double-buffer (lanes sharing a token group issue
// identical LDG addresses -> hardware dedup), w is LDG L1-hit.
// Thread tile 8 tok x 8 exp (4 f32x2 expert pairs).
// Per-(token,expert): sequential fp32 FMA chain, k ascending —
// bitwise identical to R1/R6-R13.
// ============================================================
__global__ void __launch_bounds__(NTHR, 2)
gate_kernel(const float* __restrict__ x,
            const float* __restrict__ bias_in,
            const float* __restrict__ usage_in,
            float* __restrict__ out, int T, float inv_total) {
    __shared__ float sc[BT * SSTR];
    __shared__ float bias_s[NE];
    __shared__ int   hist_s[NE];
    __shared__ int   flag_s;

    const int tid  = threadIdx.x;
    const int wid  = tid >> 5;
    const int lane = tid & 31;
    const int tgl  = lane >> 3;                // token group (0..3)
    const int eg   = lane & 7;                 // expert group
    const long long tb = (long long)blockIdx.x * BT;

    if (tid < NE) { hist_s[tid] = 0; bias_s[tid] = bias_in[tid]; }

    // this thread's 8 token rows (8 lanes share each -> LDG dedup)
    const float* xrow = x + (tb + wid * 32 + tgl * 8) * (long long)DIM;
    const float* wrow = g_wt + eg * 8;

    // x register double-buffer: [buf][token] = 4 k values
    float4 xb[2][8];
    #pragma unroll
    for (int i = 0; i < 8; i++)
        xb[0][i] = __ldcs((const float4*)(xrow + (long long)i * DIM));

    unsigned long long acc[8][4];
    #pragma unroll
    for (int t = 0; t < 8; t++)
        #pragma unroll
        for (int p = 0; p < 4; p++) acc[t][p] = 0ull;

    for (int ch = 0; ch < NCHK; ch++) {
        const int buf = ch & 1;

        // prefetch next x chunk (streaming loads, evict-first)
        if (ch + 1 < NCHK) {
            const float* xp = xrow + (ch + 1) * KC;
            #pragma unroll
            for (int i = 0; i < 8; i++)
                xb[buf ^ 1][i] =
                    __ldcs((const float4*)(xp + (long long)i * DIM));
        }

        // w: 2 LDG.128/k, L1-resident; 1-k software pipeline
        const float* wc = wrow + ch * KC * NE;
        ulonglong2 wa = *(const ulonglong2*)(wc);
        ulonglong2 wb = *(const ulonglong2*)(wc + 4);

        {   // k = 0
            ulonglong2 na = *(const ulonglong2*)(wc + NE);
            ulonglong2 nb = *(const ulonglong2*)(wc + NE + 4);
            float xs[8] = {xb[buf][0].x, xb[buf][1].x, xb[buf][2].x, xb[buf][3].x,
                           xb[buf][4].x, xb[buf][5].x, xb[buf][6].x, xb[buf][7].x};
            COMPUTE_K(xs, wa, wb);
            wa = na; wb = nb;
        }
        {   // k = 1
            ulonglong2 na = *(const ulonglong2*)(wc + 2 * NE);
            ulonglong2 nb = *(const ulonglong2*)(wc + 2 * NE + 4);
            float xs[8] = {xb[buf][0].y, xb[buf][1].y, xb[buf][2].y, xb[buf][3].y,
                           xb[buf][4].y, xb[buf][5].y, xb[buf][6].y, xb[buf][7].y};
            COMPUTE_K(xs, wa, wb);
            wa = na; wb = nb;
        }
        {   // k = 2
            ulonglong2 na = *(const ulonglong2*)(wc + 3 * NE);
            ulonglong2 nb = *(const ulonglong2*)(wc + 3 * NE + 4);
            float xs[8] = {xb[buf][0].z, xb[buf][1].z, xb[buf][2].z, xb[buf][3].z,
                           xb[buf][4].z, xb[buf][5].z, xb[buf][6].z, xb[buf][7].z};
            COMPUTE_K(xs, wa, wb);
            wa = na; wb = nb;
        }
        {   // k = 3
            float xs[8] = {xb[buf][0].w, xb[buf][1].w, xb[buf][2].w, xb[buf][3].w,
                           xb[buf][4].w, xb[buf][5].w, xb[buf][6].w, xb[buf][7].w};
            COMPUTE_K(xs, wa, wb);
        }
    }

    // ---- accumulators -> smem scores ----
    #pragma unroll
    for (int t = 0; t < 8; t++) {
        const int row = wid * 32 + tgl * 8 + t;
        #pragma unroll
        for (int p = 0; p < 4; p++) {
            float2 v = ull_as_f2(acc[t][p]);
            *(float2*)(sc + row * SSTR + eg * 8 + 2 * p) = v;
        }
    }
    __syncthreads();

    // ---- per-token epilogue: softmax + top-8 (1 token/thread) ----
    {
        float* row = sc + tid * SSTR;
        float m = -3.4e38f;
        #pragma unroll
        for (int e = 0; e < NE; e++) {
            float v = row[e] + bias_s[e];
            row[e] = v;
            m = fmaxf(m, v);
        }
        float z = 0.0f;
        #pragma unroll
        for (int e = 0; e < NE; e++)
            z += exp2f((row[e] - m) * LOG2E);
        float invz = 1.0f / z;

        unsigned long long msk = 0ull;
        float tw[TOPK]; int ti[TOPK];
        float ts = 0.0f;
        #pragma unroll 1
        for (int it = 0; it < TOPK; it++) {
            float bv = -3.4e38f; int bi = 0;
            #pragma unroll
            for (int e = 0; e < NE; e++) {
                float v = row[e];
                bool ok = (((msk >> e) & 1ull) == 0ull) && (v > bv);
                if (ok) { bv = v; bi = e; }
            }
            msk |= 1ull << bi;
            float p = exp2f((bv - m) * LOG2E) * invz;
            ts += p; tw[it] = p; ti[it] = bi;
        }
        float inv = 1.0f / (ts + 1e-8f);

        const long long tok = tb + tid;
        float* ow = out + tok * TOPK;
        float* oi = out + (long long)T * TOPK + tok * TOPK;
        *(float4*)(ow)     = make_float4(tw[0]*inv, tw[1]*inv, tw[2]*inv, tw[3]*inv);
        *(float4*)(ow + 4) = make_float4(tw[4]*inv, tw[5]*inv, tw[6]*inv, tw[7]*inv);
        *(float4*)(oi)     = make_float4((float)ti[0], (float)ti[1], (float)ti[2], (float)ti[3]);
        *(float4*)(oi + 4) = make_float4((float)ti[4], (float)ti[5], (float)ti[6], (float)ti[7]);
        #pragma unroll
        for (int k = 0; k < TOPK; k++) atomicAdd(&hist_s[ti[k]], 1);
    }
    __syncthreads();

    if (tid < NE) {
        atomicAdd(&g_hist[tid], hist_s[tid]);
        __threadfence();
    }
    __syncthreads();

    // ---- last-CTA finalize ----
    if (tid == 0) {
        int t = atomicAdd(&g_cnt, 1);
        flag_s = (t == (int)gridDim.x - 1) ? 1 : 0;
    }
    __syncthreads();
    if (flag_s) {
        __threadfence();
        if (tid < NE) {
            int cnt = atomicAdd(&g_hist[tid], 0);
            float u = (float)cnt * inv_total;
            float* out_bias  = out + 2LL * T * TOPK;
            float* out_usage = out_bias + NE;
            out_bias[tid]  = bias_in[tid] - 0.01f * (u - 1.0f / (float)NE);
            out_usage[tid] = 0.9f * usage_in[tid] + 0.1f * u;
        }
        if (tid == 0) atomicExch(&g_cnt, 0);
    }
}

// ============================================================
extern "C" void kernel_launch(void* const* d_in, const int* in_sizes, int n_in,
                              void* d_out, int out_size) {
    const float* x     = (const float*)d_in[0];   // [4, 8192, 2048]
    const float* gw    = (const float*)d_in[1];   // [64, 2048]
    const float* bias  = (const float*)d_in[2];   // [64]
    const float* usage = (const float*)d_in[3];   // [64]

    const int T = in_sizes[0] / DIM;              // 32768
    float* out = (float*)d_out;

    prep_kernel<<<32, 256>>>(gw);
    gate_kernel<<<T / BT, NTHR>>>(x, bias, usage, out, T,
                                  1.0f / (float)(T * TOPK));
}

// round 16
// speedup vs baseline: 1.2115x; 1.2115x over previous
#include <cuda_runtime.h>
#include <stdint.h>

#define DIM   2048
#define NE    64
#define TOPK  8
#define BT    256            // tokens per CTA
#define NTHR  128
#define KC    16             // k per chunk
#define NCHK  (DIM / KC)     // 128
#define WXB   (KC * 64)      // 1024 f: per-warp x buffer (64 tokens)
#define WWB   (KC * NE)      // 1024 f: per-warp w buffer
#define WREG  (2 * WXB + 2 * WWB)   // 4096 f per warp region
#define SSTR  66
#define SCFL  (BT * SSTR)    // 16896 f
#define LOG2E 1.4426950408889634f

// Transposed + bank-permuted weights [k][slot] as float4. 512 KB, L2-resident.
// Slot p of a k-row: p<8 -> experts p*8+0..3 ; p>=8 -> experts (p-8)*8+4..7.
__device__ float4 g_wt4[DIM * (NE / 4)];
__device__ int    g_hist[NE];
__device__ int    g_cnt;

// ---------------- helpers ----------------
__device__ __forceinline__ void ffma2(unsigned long long &d,
                                      unsigned long long a,
                                      unsigned long long b) {
    asm("fma.rn.f32x2 %0, %1, %2, %0;" : "+l"(d) : "l"(a), "l"(b));
}
__device__ __forceinline__ unsigned long long dup2(float w) {
    unsigned long long r;
    asm("mov.b64 %0, {%1, %1};" : "=l"(r) : "f"(w));
    return r;
}
__device__ __forceinline__ float2 ull_as_f2(unsigned long long v) {
    float2 r;
    asm("mov.b64 {%0, %1}, %2;" : "=f"(r.x), "=f"(r.y) : "l"(v));
    return r;
}
__device__ __forceinline__ void cp16(uint32_t dst_smem, const void* src) {
    asm volatile("cp.async.ca.shared.global [%0], [%1], 16;"
                 :: "r"(dst_smem), "l"(src));
}
__device__ __forceinline__ void cp_commit() {
    asm volatile("cp.async.commit_group;");
}
__device__ __forceinline__ void cp_wait0() {
    asm volatile("cp.async.wait_group 0;" ::: "memory");
}

// ============================================================
// Prep: transpose gate_weight [64][2048] -> g_wt4 [2048][16 slots]
// with the conflict-free slot permutation.
// ============================================================
__global__ void prep_kernel(const float* __restrict__ gw) {
    __shared__ float ts[64][68];
    const int t = threadIdx.x, blk = blockIdx.x;
    #pragma unroll
    for (int i = 0; i < 4; i++) {
        int idx = t + i * 256;
        int e = idx >> 4, q = idx & 15;
        float4 f = ((const float4*)gw)[e * 512 + blk * 16 + q];
        ts[e][q * 4 + 0] = f.x; ts[e][q * 4 + 1] = f.y;
        ts[e][q * 4 + 2] = f.z; ts[e][q * 4 + 3] = f.w;
    }
    __syncthreads();
    #pragma unroll
    for (int i = 0; i < 4; i++) {
        int idx = t + i * 256;
        int k = idx >> 4, p = idx & 15;
        int base = (p < 8) ? p * 8 : (p - 8) * 8 + 4;
        g_wt4[(blk * 64 + k) * 16 + p] =
            make_float4(ts[base + 0][k], ts[base + 1][k],
                        ts[base + 2][k], ts[base + 3][k]);
    }
    if (blk == 0 && t < NE) g_hist[t] = 0;
    if (blk == 0 && t == 0) g_cnt = 0;
}

// ============================================================
// Fused gate kernel. CTA: 256 tok x 64 exp, 128 threads; grid 128.
// Warp owns 64 tokens with PRIVATE double-buffered x/w smem — no
// __syncthreads in the mainloop. Thread tile 16 tok x 8 exp:
// per k, 96B smem read per thread feeds 64 FFMA2 (fma-bound).
// Per-(token,expert): sequential fp32 FMA chain, k ascending —
// bitwise identical to R1/R6-R14.
// ============================================================
__global__ void __launch_bounds__(NTHR, 1)
gate_kernel(const float* __restrict__ x,
            const float* __restrict__ bias_in,
            const float* __restrict__ usage_in,
            float* __restrict__ out, int T, float inv_total) {
    extern __shared__ float sm[];
    float* sc     = sm;                        // [256][66] (aliases pipeline)
    float* bias_s = sm + SCFL;                 // [64]
    int*   hist_s = (int*)(bias_s + NE);       // [64]
    int*   flag_s = hist_s + NE;

    const int tid  = threadIdx.x;
    const int wid  = tid >> 5;                 // 0..3
    const int lane = tid & 31;
    const int tg   = lane >> 3;                // token group (0..3) -> 16 tok
    const int eg   = lane & 7;                 // expert group
    const long long tb = (long long)blockIdx.x * BT;

    if (tid < NE) { hist_s[tid] = 0; bias_s[tid] = bias_in[tid]; }

    float* xw = sm + wid * WREG;               // [2][KC][64]
    float* ww = xw + 2 * WXB;                  // [2][KC][64]
    const uint32_t ww_u32 = (uint32_t)__cvta_generic_to_shared(ww);
    // warp owns tokens wid*64 .. +63; this thread stages rows lane, lane+32
    const float* xg0 = x + (tb + wid * 64 + lane) * (long long)DIM;
    const float* xg1 = xg0 + 32 * (long long)DIM;

    // ---- stage chunk 0 (warp-local) ----
    {
        #pragma unroll
        for (int j = 0; j < 4; j++) {
            float4 a = *(const float4*)(xg0 + j * 4);
            float4 b = *(const float4*)(xg1 + j * 4);
            xw[(j * 4 + 0) * 64 + lane] = a.x;
            xw[(j * 4 + 1) * 64 + lane] = a.y;
            xw[(j * 4 + 2) * 64 + lane] = a.z;
            xw[(j * 4 + 3) * 64 + lane] = a.w;
            xw[(j * 4 + 0) * 64 + lane + 32] = b.x;
            xw[(j * 4 + 1) * 64 + lane + 32] = b.y;
            xw[(j * 4 + 2) * 64 + lane + 32] = b.z;
            xw[(j * 4 + 3) * 64 + lane + 32] = b.w;
        }
        #pragma unroll
        for (int i = 0; i < 8; i++)
            cp16(ww_u32 + (lane + i * 32) * 16, &g_wt4[lane + i * 32]);
        cp_commit();
    }

    unsigned long long acc[16][4];
    #pragma unroll
    for (int t = 0; t < 16; t++)
        #pragma unroll
        for (int p = 0; p < 4; p++) acc[t][p] = 0ull;

    cp_wait0();
    __syncwarp();

    for (int ch = 0; ch < NCHK; ch++) {
        const int buf = ch & 1;

        // next-chunk producers (warp-local)
        float4 xr0[4], xr1[4];
        if (ch + 1 < NCHK) {
            const float* xp0 = xg0 + (ch + 1) * KC;
            const float* xp1 = xg1 + (ch + 1) * KC;
            #pragma unroll
            for (int j = 0; j < 4; j++) {
                xr0[j] = *(const float4*)(xp0 + j * 4);
                xr1[j] = *(const float4*)(xp1 + j * 4);
            }
            const uint32_t wdst = ww_u32 + (buf ^ 1) * (WWB * 4);
            const float4* wsrc = &g_wt4[(ch + 1) * 256];
            #pragma unroll
            for (int i = 0; i < 8; i++)
                cp16(wdst + (lane + i * 32) * 16, wsrc + lane + i * 32);
            cp_commit();
        }

        const float* xb = xw + buf * WXB + tg * 16;
        const float* wb = ww + buf * WWB + eg * 4;   // permuted, conflict-free

        // software-pipelined inner loop: 1-k operand double buffer
        float4 xs0 = *(const float4*)(xb);
        float4 xs1 = *(const float4*)(xb + 4);
        float4 xs2 = *(const float4*)(xb + 8);
        float4 xs3 = *(const float4*)(xb + 12);
        ulonglong2 wa = *(const ulonglong2*)(wb);
        ulonglong2 wc = *(const ulonglong2*)(wb + 32);

        #pragma unroll
        for (int k = 0; k < KC; k++) {
            float4 n0, n1, n2, n3; ulonglong2 na, nc;
            if (k + 1 < KC) {
                n0 = *(const float4*)(xb + (k + 1) * 64);
                n1 = *(const float4*)(xb + (k + 1) * 64 + 4);
                n2 = *(const float4*)(xb + (k + 1) * 64 + 8);
                n3 = *(const float4*)(xb + (k + 1) * 64 + 12);
                na = *(const ulonglong2*)(wb + (k + 1) * NE);
                nc = *(const ulonglong2*)(wb + (k + 1) * NE + 32);
            }
            {
                float xs[16] = {xs0.x, xs0.y, xs0.z, xs0.w,
                                xs1.x, xs1.y, xs1.z, xs1.w,
                                xs2.x, xs2.y, xs2.z, xs2.w,
                                xs3.x, xs3.y, xs3.z, xs3.w};
                #pragma unroll
                for (int t = 0; t < 16; t++) {
                    unsigned long long xd = dup2(xs[t]);
                    ffma2(acc[t][0], xd, wa.x);
                    ffma2(acc[t][1], xd, wa.y);
                    ffma2(acc[t][2], xd, wc.x);
                    ffma2(acc[t][3], xd, wc.y);
                }
            }
            if (k + 1 < KC) {
                xs0 = n0; xs1 = n1; xs2 = n2; xs3 = n3;
                wa = na; wc = nc;
            }
        }

        // stage next x chunk (warp-local STS transpose)
        if (ch + 1 < NCHK) {
            float* xd = xw + (buf ^ 1) * WXB;
            #pragma unroll
            for (int j = 0; j < 4; j++) {
                xd[(j * 4 + 0) * 64 + lane] = xr0[j].x;
                xd[(j * 4 + 1) * 64 + lane] = xr0[j].y;
                xd[(j * 4 + 2) * 64 + lane] = xr0[j].z;
                xd[(j * 4 + 3) * 64 + lane] = xr0[j].w;
                xd[(j * 4 + 0) * 64 + lane + 32] = xr1[j].x;
                xd[(j * 4 + 1) * 64 + lane + 32] = xr1[j].y;
                xd[(j * 4 + 2) * 64 + lane + 32] = xr1[j].z;
                xd[(j * 4 + 3) * 64 + lane + 32] = xr1[j].w;
            }
            cp_wait0();
        }
        __syncwarp();
    }

    __syncthreads();   // pipeline regions become score space

    // ---- accumulators -> smem scores ----
    #pragma unroll
    for (int t = 0; t < 16; t++) {
        const int row = wid * 64 + tg * 16 + t;
        #pragma unroll
        for (int p = 0; p < 4; p++) {
            float2 v = ull_as_f2(acc[t][p]);
            *(float2*)(sc + row * SSTR + eg * 8 + 2 * p) = v;
        }
    }
    __syncthreads();

    // ---- per-token epilogue: softmax + top-8 (2 tokens/thread) ----
    for (int tt = tid; tt < BT; tt += NTHR) {
        float* row = sc + tt * SSTR;
        float m = -3.4e38f;
        #pragma unroll
        for (int e = 0; e < NE; e++) {
            float v = row[e] + bias_s[e];
            row[e] = v;
            m = fmaxf(m, v);
        }
        float z = 0.0f;
        #pragma unroll
        for (int e = 0; e < NE; e++)
            z += exp2f((row[e] - m) * LOG2E);
        float invz = 1.0f / z;

        unsigned long long msk = 0ull;
        float tw[TOPK]; int ti[TOPK];
        float ts = 0.0f;
        #pragma unroll 1
        for (int it = 0; it < TOPK; it++) {
            float bv = -3.4e38f; int bi = 0;
            #pragma unroll
            for (int e = 0; e < NE; e++) {
                float v = row[e];
                bool ok = (((msk >> e) & 1ull) == 0ull) && (v > bv);
                if (ok) { bv = v; bi = e; }
            }
            msk |= 1ull << bi;
            float p = exp2f((bv - m) * LOG2E) * invz;
            ts += p; tw[it] = p; ti[it] = bi;
        }
        float inv = 1.0f / (ts + 1e-8f);

        const long long tok = tb + tt;
        float* ow = out + tok * TOPK;
        float* oi = out + (long long)T * TOPK + tok * TOPK;
        *(float4*)(ow)     = make_float4(tw[0]*inv, tw[1]*inv, tw[2]*inv, tw[3]*inv);
        *(float4*)(ow + 4) = make_float4(tw[4]*inv, tw[5]*inv, tw[6]*inv, tw[7]*inv);
        *(float4*)(oi)     = make_float4((float)ti[0], (float)ti[1], (float)ti[2], (float)ti[3]);
        *(float4*)(oi + 4) = make_float4((float)ti[4], (float)ti[5], (float)ti[6], (float)ti[7]);
        #pragma unroll
        for (int k = 0; k < TOPK; k++) atomicAdd(&hist_s[ti[k]], 1);
    }
    __syncthreads();

    if (tid < NE) {
        atomicAdd(&g_hist[tid], hist_s[tid]);
        __threadfence();
    }
    __syncthreads();

    // ---- last-CTA finalize ----
    if (tid == 0) {
        int t = atomicAdd(&g_cnt, 1);
        *flag_s = (t == (int)gridDim.x - 1) ? 1 : 0;
    }
    __syncthreads();
    if (*flag_s) {
        __threadfence();
        if (tid < NE) {
            int cnt = atomicAdd(&g_hist[tid], 0);
            float u = (float)cnt * inv_total;
            float* out_bias  = out + 2LL * T * TOPK;
            float* out_usage = out_bias + NE;
            out_bias[tid]  = bias_in[tid] - 0.01f * (u - 1.0f / (float)NE);
            out_usage[tid] = 0.9f * usage_in[tid] + 0.1f * u;
        }
        if (tid == 0) atomicExch(&g_cnt, 0);
    }
}

// ============================================================
extern "C" void kernel_launch(void* const* d_in, const int* in_sizes, int n_in,
                              void* d_out, int out_size) {
    const float* x     = (const float*)d_in[0];   // [4, 8192, 2048]
    const float* gw    = (const float*)d_in[1];   // [64, 2048]
    const float* bias  = (const float*)d_in[2];   // [64]
    const float* usage = (const float*)d_in[3];   // [64]

    const int T = in_sizes[0] / DIM;              // 32768
    float* out = (float*)d_out;

    const int smem_bytes = (SCFL + NE) * 4 + NE * 4 + 16;
    cudaFuncSetAttribute(gate_kernel,
                         cudaFuncAttributeMaxDynamicSharedMemorySize, smem_bytes);

    prep_kernel<<<32, 256>>>(gw);
    gate_kernel<<<T / BT, NTHR, smem_bytes>>>(x, bias, usage, out, T,
                                              1.0f / (float)(T * TOPK));
}